// round 14
// baseline (speedup 1.0000x reference)
#include <cuda_runtime.h>
#include <cuda_bf16.h>
#include <math.h>
#include <stdint.h>

#define Bsz  256
#define Tsz  128
#define Hsz  1024
#define G3   3072
#define Vsz  348
#define Vpad 384
#define Kd   1024
#define NBLK 296                         // 2 CTAs per SM
#define NTHR 256
#define WSEG 3145728   // 3072*1024
#define BH   (Bsz * Hsz)

// GEMM unit: 128(m) x 128(n), BK=32, 256 threads = 8 warps (2m x 4n), warp tile 64x32
// 5-stage cp.async ring, one __syncthreads per 32-K chunk, 4-chunk lookahead.
#define TM 128
#define TN 128
#define PITCH 80                         // smem row pitch bytes (32 bf16 + pad)
#define STAGE_BYTES ((TM + TN) * PITCH)  // 20480
#define NSTAGE 5
#define SMEM_DYN (NSTAGE * STAGE_BYTES + 256)   // 102656/CTA; x2 = 205312 <= 228KB

// ---------------- scratch (device globals; no allocs allowed) ----------------
__device__ __nv_bfloat16  g_gi1[(size_t)Tsz * Bsz * G3];
__device__ __nv_bfloat16  g_xb[(size_t)Tsz * Bsz * Kd];
__device__ __nv_bfloat16  g_wb[6 * (size_t)WSEG];
__device__ __nv_bfloat16  g_wout[Vpad * Kd];
__device__ __nv_bfloat16  g_gh1[Bsz * G3];
__device__ __nv_bfloat16  g_gi2[Bsz * G3], g_gh2[Bsz * G3];
__device__ __nv_bfloat16  g_gi3[Bsz * G3], g_gh3[Bsz * G3];
__device__ float          g_h1[BH], g_h2[BH], g_h3[BH];
__device__ __nv_bfloat16  g_h1b[BH], g_h2b[BH], g_h3b[BH];
__device__ float          g_logits[2 * Bsz * Vpad];        // double-buffered by step parity
__device__ unsigned       g_bar_count;   // monotonic
__device__ unsigned       g_bar_gen;     // monotonic

namespace {
struct Boot {
    Boot() { void* p = nullptr; cudaGetSymbolAddress(&p, g_gi1); }
};
static Boot boot_;
}

// ---------------- low-level helpers ----------------
__device__ __forceinline__ uint32_t smem_u32(const void* p) {
    return (uint32_t)__cvta_generic_to_shared(p);
}
__device__ __forceinline__ void cpa16s(uint32_t saddr, const void* g) {
    asm volatile("cp.async.cg.shared.global [%0], [%1], 16;" :: "r"(saddr), "l"(g));
}
__device__ __forceinline__ void cpa_commit() {
    asm volatile("cp.async.commit_group;");
}
template <int N>
__device__ __forceinline__ void cpa_wait() {
    asm volatile("cp.async.wait_group %0;" :: "n"(N));
}
__device__ __forceinline__ void ldsm_x4(uint32_t* r, uint32_t a) {
    asm volatile("ldmatrix.sync.aligned.m8n8.x4.shared.b16 {%0,%1,%2,%3}, [%4];"
        : "=r"(r[0]), "=r"(r[1]), "=r"(r[2]), "=r"(r[3]) : "r"(a));
}
__device__ __forceinline__ void mma16816(float* c, const uint32_t* a, uint32_t b0, uint32_t b1) {
    asm volatile(
        "mma.sync.aligned.m16n8k16.row.col.f32.bf16.bf16.f32 "
        "{%0,%1,%2,%3},{%4,%5,%6,%7},{%8,%9},{%0,%1,%2,%3};"
        : "+f"(c[0]), "+f"(c[1]), "+f"(c[2]), "+f"(c[3])
        : "r"(a[0]), "r"(a[1]), "r"(a[2]), "r"(a[3]), "r"(b0), "r"(b1));
}
__device__ __forceinline__ void store_pair(float* p, float a, float b) {
    *(float2*)p = make_float2(a, b);
}
__device__ __forceinline__ void store_pair(__nv_bfloat16* p, float a, float b) {
    *(__nv_bfloat162*)p = __floats2bfloat162_rn(a, b);
}
__device__ __forceinline__ float2 bf2(const __nv_bfloat16* p) {
    __nv_bfloat162 v = *(const __nv_bfloat162*)p;
    return make_float2(__bfloat162float(v.x), __bfloat162float(v.y));
}
__device__ __forceinline__ float tanh_fast(float x) {
    float y; asm("tanh.approx.f32 %0, %1;" : "=f"(y) : "f"(x)); return y;
}

// ---------------- grid barrier (release/acquire, monotonic) ----------------
__device__ __forceinline__ void grid_barrier(unsigned& gen) {
    __syncthreads();
    if (threadIdx.x == 0) {
        unsigned target = gen + 1;
        unsigned old;
        asm volatile("atom.add.acq_rel.gpu.u32 %0, [%1], 1;"
                     : "=r"(old) : "l"(&g_bar_count) : "memory");
        if (old == target * NBLK - 1) {
            asm volatile("st.release.gpu.u32 [%0], %1;"
                         :: "l"(&g_bar_gen), "r"(target) : "memory");
        } else {
            unsigned cur;
            do {
                asm volatile("ld.acquire.gpu.u32 %0, [%1];"
                             : "=r"(cur) : "l"(&g_bar_gen) : "memory");
            } while (cur < target);
        }
    }
    gen++;
    __syncthreads();
}

// ---------------- mma.sync GEMM unit: C[128 x 128] = A[128xK] @ W[128xK]^T ----------------
// A bf16 [M][K] row-major; W bf16 [N][K] row-major (= B col-major for mma.row.col).
// 256 threads = 8 warps (2m x 4n), warp tile 64x32.
// 5-stage cp.async ring; one __syncthreads per 32-K chunk; 4-chunk lookahead.
template <typename CT>
__device__ __forceinline__ void mma_unit(
    const __nv_bfloat16* __restrict__ A,
    const __nv_bfloat16* __restrict__ W,
    CT* __restrict__ C, int ldC,
    int m0, int n0, uint32_t smem0)
{
    const int tid  = threadIdx.x;
    const int lane = tid & 31;
    const int wid  = tid >> 5;          // 0..7
    const int wm   = (wid & 1) * 64;    // warp m-slab
    const int wn   = (wid >> 1) * 32;   // warp n-slab

    // ---- per-thread cp.async mapping: 2 A segs + 2 W segs ----
    const char* baseA = (const char*)(A + (size_t)m0 * Kd);
    const char* baseW = (const char*)(W + (size_t)n0 * Kd);
    uint32_t sA_off[2], gA_off[2], sW_off[2], gW_off[2];
    #pragma unroll
    for (int i = 0; i < 2; i++) {        // A: 128 rows x 4 x 16B = 512 segs
        int seg = tid + i * NTHR;
        int row = seg >> 2, part = seg & 3;
        sA_off[i] = row * PITCH + part * 16;
        gA_off[i] = row * (Kd * 2) + part * 16;
        sW_off[i] = TM * PITCH + sA_off[i];
        gW_off[i] = gA_off[i];
    }

    float acc[4][4][4];
    #pragma unroll
    for (int mi = 0; mi < 4; mi++)
        #pragma unroll
        for (int ni = 0; ni < 4; ni++)
            #pragma unroll
            for (int q = 0; q < 4; q++) acc[mi][ni][q] = 0.f;

    const int a_r = (lane & 7) + (lane & 8);
    const int a_k = (lane >> 4) * 16;
    const int b_r = (lane & 7) + ((lane >> 4) << 3);
    const int b_k = (lane & 8) ? 16 : 0;

    auto issue = [&](int c) {
        uint32_t st = smem0 + (uint32_t)(c % NSTAGE) * STAGE_BYTES;
        uint32_t gadd = (uint32_t)c * 64;   // 32 bf16 = 64 bytes per chunk
        cpa16s(st + sA_off[0], baseA + gA_off[0] + gadd);
        cpa16s(st + sA_off[1], baseA + gA_off[1] + gadd);
        cpa16s(st + sW_off[0], baseW + gW_off[0] + gadd);
        cpa16s(st + sW_off[1], baseW + gW_off[1] + gadd);
        cpa_commit();
    };
    issue(0); issue(1); issue(2); issue(3);

    #pragma unroll 1
    for (int c = 0; c < 32; c++) {
        if (c < 29) cpa_wait<3>(); else if (c == 29) cpa_wait<2>();
        else if (c == 30) cpa_wait<1>(); else cpa_wait<0>();
        __syncthreads();
        // stage (c+4)%NSTAGE == (c-1)%NSTAGE: its data was consumed in
        // iteration c-1, drained by the __syncthreads above.
        if (c + 4 < 32) issue(c + 4);
        uint32_t st = smem0 + (uint32_t)(c % NSTAGE) * STAGE_BYTES;
        uint32_t sB = st + TM * PITCH;
        #pragma unroll
        for (int ks = 0; ks < 2; ks++) {
            uint32_t a4[4][4], b4[2][4];
            #pragma unroll
            for (int mi = 0; mi < 4; mi++)
                ldsm_x4(a4[mi], st + (wm + mi * 16 + a_r) * PITCH + a_k + ks * 32);
            #pragma unroll
            for (int bi = 0; bi < 2; bi++)
                ldsm_x4(b4[bi], sB + (wn + bi * 16 + b_r) * PITCH + b_k + ks * 32);
            #pragma unroll
            for (int mi = 0; mi < 4; mi++)
                #pragma unroll
                for (int bi = 0; bi < 2; bi++) {
                    mma16816(acc[mi][2 * bi],     a4[mi], b4[bi][0], b4[bi][1]);
                    mma16816(acc[mi][2 * bi + 1], a4[mi], b4[bi][2], b4[bi][3]);
                }
        }
    }

    const int er = lane >> 2;
    const int ec = (lane & 3) * 2;
    #pragma unroll
    for (int mi = 0; mi < 4; mi++) {
        #pragma unroll
        for (int ni = 0; ni < 4; ni++) {
            CT* p = C + (size_t)(m0 + wm + mi * 16 + er) * ldC + n0 + wn + ni * 8 + ec;
            store_pair(p,           acc[mi][ni][0], acc[mi][ni][1]);
            store_pair(p + 8 * ldC, acc[mi][ni][2], acc[mi][ni][3]);
        }
    }
    __syncthreads();
}

// ---------------- phase helpers ----------------
__device__ __forceinline__ float sigmoidf_(float x) { return 1.f / (1.f + __expf(-x)); }

__device__ __forceinline__ void gate_phase(
    const __nv_bfloat16* __restrict__ gi, const __nv_bfloat16* __restrict__ gh,
    const float* __restrict__ bi, const float* __restrict__ bh,
    float* __restrict__ h, __nv_bfloat16* __restrict__ hb)
{
    const int NP = BH / 2;
    for (int p = blockIdx.x * blockDim.x + threadIdx.x;
         p < NP; p += gridDim.x * blockDim.x) {
        int b = p >> 9;
        int j = (p & 511) * 2;
        const __nv_bfloat16* gib = gi + (size_t)b * G3;
        const __nv_bfloat16* ghb = gh + (size_t)b * G3;
        float2 ir = bf2(gib + j), iz = bf2(gib + 1024 + j), in2 = bf2(gib + 2048 + j);
        float2 hr = bf2(ghb + j), hz = bf2(ghb + 1024 + j), hn = bf2(ghb + 2048 + j);
        float2 br0 = *(const float2*)(bi + j), bz0 = *(const float2*)(bi + 1024 + j),
               bn0 = *(const float2*)(bi + 2048 + j);
        float2 br1 = *(const float2*)(bh + j), bz1 = *(const float2*)(bh + 1024 + j),
               bn1 = *(const float2*)(bh + 2048 + j);
        int idx = b * Hsz + j;
        float2 hp = *(const float2*)(h + idx);

        float r0 = sigmoidf_(ir.x + br0.x + hr.x + br1.x);
        float z0 = sigmoidf_(iz.x + bz0.x + hz.x + bz1.x);
        float n0 = tanh_fast(in2.x + bn0.x + r0 * (hn.x + bn1.x));
        float h0 = (1.f - z0) * n0 + z0 * hp.x;

        float r1 = sigmoidf_(ir.y + br0.y + hr.y + br1.y);
        float z1 = sigmoidf_(iz.y + bz0.y + hz.y + bz1.y);
        float n1 = tanh_fast(in2.y + bn0.y + r1 * (hn.y + bn1.y));
        float h1 = (1.f - z1) * n1 + z1 * hp.y;

        *(float2*)(h + idx) = make_float2(h0, h1);
        *(__nv_bfloat162*)(hb + idx) = __floats2bfloat162_rn(h0, h1);
    }
}

// warp-per-row logprob; runs in the GEMM phase on one block (no __syncthreads)
__device__ __forceinline__ void logprob_warp(
    int t, int par, const int* __restrict__ target,
    const float* __restrict__ b_out, float* __restrict__ lp)
{
    const int lane = threadIdx.x & 31;
    const int wid  = threadIdx.x >> 5;          // 0..7
    const float* L = g_logits + (size_t)par * Bsz * Vpad;
    for (int b = wid; b < Bsz; b += NTHR / 32) {
        const float* row = L + (size_t)b * Vpad;
        float m = -1e30f;
        for (int v = lane; v < Vsz; v += 32) m = fmaxf(m, row[v] + b_out[v]);
        #pragma unroll
        for (int o = 16; o; o >>= 1) m = fmaxf(m, __shfl_xor_sync(0xffffffffu, m, o));
        float ss = 0.f;
        for (int v = lane; v < Vsz; v += 32) ss += __expf(row[v] + b_out[v] - m);
        #pragma unroll
        for (int o = 16; o; o >>= 1) ss += __shfl_xor_sync(0xffffffffu, ss, o);
        if (lane == 0) {
            int tg = target[b * Tsz + t];
            lp[b] += row[tg] + b_out[tg] - (m + __logf(ss));
        }
    }
}

// ---------------- persistent wavefront kernel (2 CTAs/SM, 1 unit each) ----------------
// Super-step s GEMM phase (all independent; 295/296 blocks busy):
//   gh1(t=s), gi2+gh2(t=s-1), gi3+gh3(t=s-2), logits(t=s-3) -> parity s&1,
//   gi1(t=s+1), and block 294: logprob(t=s-4) from parity (s-1)&1.
// Unit grid per 256x3072 GEMM: 2 m-tiles x 24 n-tiles = 48 units of 128x128.
// Gate phase: gate1(s), gate2(s-1), gate3(s-2). 2 barriers/step.
__global__ __launch_bounds__(NTHR, 2) void recur_kernel(
    const int* __restrict__ target,
    const float* __restrict__ b_ih1, const float* __restrict__ b_hh1,
    const float* __restrict__ b_ih2, const float* __restrict__ b_hh2,
    const float* __restrict__ b_ih3, const float* __restrict__ b_hh3,
    const float* __restrict__ b_out,
    float* __restrict__ lp)
{
    extern __shared__ char dsm[];
    const uint32_t smem0 = (smem_u32(dsm) + 127u) & ~127u;
    unsigned gen = 0;
    const int u = blockIdx.x;
    const int g = u / 48;                 // 0..5 for u<288
    const int v = u % 48;
    const int m0 = (v / 24) * TM;
    const int n0 = (v % 24) * TN;

    for (int s = -1; s < Tsz + 4; s++) {
        // ---- GEMM phase ----
        if (u < 288) {
            switch (g) {
            case 0: if (s >= 0 && s < Tsz)
                        mma_unit(g_h1b, g_wb + 1 * (size_t)WSEG, g_gh1, G3, m0, n0, smem0);
                    break;
            case 1: if (s >= 1 && s <= Tsz)
                        mma_unit(g_h1b, g_wb + 2 * (size_t)WSEG, g_gi2, G3, m0, n0, smem0);
                    break;
            case 2: if (s >= 1 && s <= Tsz)
                        mma_unit(g_h2b, g_wb + 3 * (size_t)WSEG, g_gh2, G3, m0, n0, smem0);
                    break;
            case 3: if (s >= 2 && s <= Tsz + 1)
                        mma_unit(g_h2b, g_wb + 4 * (size_t)WSEG, g_gi3, G3, m0, n0, smem0);
                    break;
            case 4: if (s >= 2 && s <= Tsz + 1)
                        mma_unit(g_h3b, g_wb + 5 * (size_t)WSEG, g_gh3, G3, m0, n0, smem0);
                    break;
            default: {
                int t1 = s + 1;                   // gi1 for the NEXT super-step
                if (t1 >= 0 && t1 < Tsz)
                    mma_unit(g_xb + (size_t)t1 * Bsz * Kd, g_wb /* w_ih1 */,
                             g_gi1 + (size_t)t1 * Bsz * G3, G3, m0, n0, smem0);
            }       break;
            }
        } else if (u < 294) {
            const int w = u - 288;                // 2m x 3n tiles of 128x128
            if (s >= 3 && s <= Tsz + 2)
                mma_unit(g_h3b, g_wout,
                         g_logits + (size_t)(s & 1) * Bsz * Vpad, Vpad,
                         (w / 3) * TM, (w % 3) * TN, smem0);
        } else if (u == 294) {
            if (s >= 4 && s <= Tsz + 3)
                logprob_warp(s - 4, (s - 1) & 1, target, b_out, lp);
        }
        grid_barrier(gen);

        // ---- gate phase ----
        if (s >= 0 && s < Tsz)
            gate_phase(g_gi1 + (size_t)s * Bsz * G3, g_gh1, b_ih1, b_hh1, g_h1, g_h1b);
        if (s >= 1 && s <= Tsz)
            gate_phase(g_gi2, g_gh2, b_ih2, b_hh2, g_h2, g_h2b);
        if (s >= 2 && s <= Tsz + 1)
            gate_phase(g_gi3, g_gh3, b_ih3, b_hh3, g_h3, g_h3b);
        grid_barrier(gen);
    }
}

// ---------------- setup kernels ----------------
__global__ __launch_bounds__(256) void init_misc(const float* __restrict__ w_out,
                                                 float* __restrict__ lp)
{
    for (int i = blockIdx.x * blockDim.x + threadIdx.x;
         i < Vpad * Kd; i += gridDim.x * blockDim.x) {
        int row = i >> 10;
        g_wout[i] = (row < Vsz) ? __float2bfloat16(w_out[i]) : __float2bfloat16(0.f);
        if (i < BH) {
            g_h1[i] = 0.f; g_h2[i] = 0.f; g_h3[i] = 0.f;
            __nv_bfloat16 z = __float2bfloat16(0.f);
            g_h1b[i] = z; g_h2b[i] = z; g_h3b[i] = z;
        }
        if (i < Bsz) lp[i] = 0.f;
        if (i == 0) { g_bar_count = 0u; g_bar_gen = 0u; }
    }
}

__global__ __launch_bounds__(256) void conv_weights(
    const float* __restrict__ w0, const float* __restrict__ w1,
    const float* __restrict__ w2, const float* __restrict__ w3,
    const float* __restrict__ w4, const float* __restrict__ w5)
{
    for (size_t i = (size_t)blockIdx.x * blockDim.x + threadIdx.x;
         i < 6 * (size_t)WSEG; i += (size_t)gridDim.x * blockDim.x) {
        int seg = (int)(i / WSEG);
        size_t off = i % WSEG;
        const float* s = seg == 0 ? w0 : seg == 1 ? w1 : seg == 2 ? w2
                       : seg == 3 ? w3 : seg == 4 ? w4 : w5;
        g_wb[i] = __float2bfloat16(s[off]);
    }
}

__global__ __launch_bounds__(256) void gather_x(
    const int* __restrict__ target, const int* __restrict__ bosp,
    const float* __restrict__ emb)
{
    const int nq = Tsz * Bsz * (Kd / 4);
    for (int i = blockIdx.x * blockDim.x + threadIdx.x; i < nq; i += gridDim.x * blockDim.x) {
        int m  = i / (Kd / 4);
        int kq = i % (Kd / 4);
        int t = m >> 8, b = m & 255;
        int tok = (t == 0) ? bosp[0] : target[(b << 7) + t - 1];
        float4 v = *(const float4*)(emb + (size_t)tok * Kd + kq * 4);
        __nv_bfloat16* dst = g_xb + (size_t)m * Kd + kq * 4;
        *(__nv_bfloat162*)(dst)     = __floats2bfloat162_rn(v.x, v.y);
        *(__nv_bfloat162*)(dst + 2) = __floats2bfloat162_rn(v.z, v.w);
    }
}

// ---------------- launch ----------------
extern "C" void kernel_launch(void* const* d_in, const int* in_sizes, int n_in,
                              void* d_out, int out_size)
{
    (void)in_sizes; (void)n_in; (void)out_size;
    const int*   target = (const int*)  d_in[0];
    const int*   bos    = (const int*)  d_in[1];
    const float* emb    = (const float*)d_in[2];
    const float* w_ih1  = (const float*)d_in[3];
    const float* w_hh1  = (const float*)d_in[4];
    const float* b_ih1  = (const float*)d_in[5];
    const float* b_hh1  = (const float*)d_in[6];
    const float* w_ih2  = (const float*)d_in[7];
    const float* w_hh2  = (const float*)d_in[8];
    const float* b_ih2  = (const float*)d_in[9];
    const float* b_hh2  = (const float*)d_in[10];
    const float* w_ih3  = (const float*)d_in[11];
    const float* w_hh3  = (const float*)d_in[12];
    const float* b_ih3  = (const float*)d_in[13];
    const float* b_hh3  = (const float*)d_in[14];
    const float* w_out  = (const float*)d_in[15];
    const float* b_out  = (const float*)d_in[16];
    float* lp = (float*)d_out;

    cudaFuncSetAttribute(recur_kernel,
        cudaFuncAttributeMaxDynamicSharedMemorySize, SMEM_DYN);
    cudaFuncSetAttribute(recur_kernel,
        cudaFuncAttributePreferredSharedMemoryCarveout, 100);

    init_misc<<<(Vpad * Kd + 255) / 256, 256>>>(w_out, lp);
    conv_weights<<<8192, 256>>>(w_ih1, w_hh1, w_ih2, w_hh2, w_ih3, w_hh3);
    gather_x<<<8192, 256>>>(target, bos, emb);

    recur_kernel<<<NBLK, NTHR, SMEM_DYN>>>(target,
                                b_ih1, b_hh1, b_ih2, b_hh2, b_ih3, b_hh3,
                                b_out, lp);
}

// round 15
// speedup vs baseline: 1.1291x; 1.1291x over previous
#include <cuda_runtime.h>
#include <cuda_bf16.h>
#include <math.h>
#include <stdint.h>

#define Bsz  256
#define Tsz  128
#define Hsz  1024
#define G3   3072
#define Vsz  348
#define Vpad 384
#define Kd   1024
#define NBLK 148
#define NTHR 512
#define WSEG 3145728   // 3072*1024
#define BH   (Bsz * Hsz)

#define QSCALE 16.f            // fp8 quantization scale (both operands)
#define QINV   (1.f / 256.f)   // preactivation descale

// GEMM config: BM=256 (=full M), BN=128, fp8 K-chunk = 64 elems (64B/row),
// 512 threads, warp tile 64x32, 6-stage cp.async ring, 1 sync per chunk.
#define BM 256
#define BN 128
#define PITCH 80                         // smem row pitch bytes (64B data + pad)
#define STAGE_BYTES ((BM + BN) * PITCH)  // 30720
#define NSTAGE 6
#define SMEM_DYN (NSTAGE * STAGE_BYTES + 256)   // 184832

// ---------------- scratch (device globals; no allocs allowed) ----------------
__device__ __nv_bfloat16  g_gi1[(size_t)Tsz * Bsz * G3];   // scaled x256
__device__ uint8_t        g_xb[(size_t)Tsz * Bsz * Kd];    // e4m3, x16
__device__ uint8_t        g_wb[6 * (size_t)WSEG];          // e4m3, x16
__device__ uint8_t        g_wout[Vpad * Kd];               // e4m3, x16
__device__ __nv_bfloat16  g_gh1[Bsz * G3];                 // scaled x256
__device__ __nv_bfloat16  g_gi2[Bsz * G3], g_gh2[Bsz * G3];
__device__ __nv_bfloat16  g_gi3[Bsz * G3], g_gh3[Bsz * G3];
__device__ float          g_h1[BH], g_h2[BH], g_h3[BH];
__device__ uint8_t        g_h1b[BH], g_h2b[BH], g_h3b[BH]; // e4m3, x16
__device__ float          g_logits[2 * Bsz * Vpad];        // scaled x256, parity buffers
__device__ unsigned       g_bar_count;   // monotonic
__device__ unsigned       g_bar_gen;     // monotonic

namespace {
struct Boot {
    Boot() { void* p = nullptr; cudaGetSymbolAddress(&p, g_gi1); }
};
static Boot boot_;
}

// ---------------- low-level helpers ----------------
__device__ __forceinline__ uint32_t smem_u32(const void* p) {
    return (uint32_t)__cvta_generic_to_shared(p);
}
__device__ __forceinline__ void cpa16s(uint32_t saddr, const void* g) {
    asm volatile("cp.async.cg.shared.global [%0], [%1], 16;" :: "r"(saddr), "l"(g));
}
__device__ __forceinline__ void cpa_commit() {
    asm volatile("cp.async.commit_group;");
}
template <int N>
__device__ __forceinline__ void cpa_wait() {
    asm volatile("cp.async.wait_group %0;" :: "n"(N));
}
__device__ __forceinline__ void ldsm_x4(uint32_t* r, uint32_t a) {
    asm volatile("ldmatrix.sync.aligned.m8n8.x4.shared.b16 {%0,%1,%2,%3}, [%4];"
        : "=r"(r[0]), "=r"(r[1]), "=r"(r[2]), "=r"(r[3]) : "r"(a));
}
// fp8 e4m3 MMA: D[16x8] += A[16x32] * B[8x32]^T, fp32 accum
__device__ __forceinline__ void mma16832(float* c, const uint32_t* a, uint32_t b0, uint32_t b1) {
    asm volatile(
        "mma.sync.aligned.m16n8k32.row.col.f32.e4m3.e4m3.f32 "
        "{%0,%1,%2,%3},{%4,%5,%6,%7},{%8,%9},{%0,%1,%2,%3};"
        : "+f"(c[0]), "+f"(c[1]), "+f"(c[2]), "+f"(c[3])
        : "r"(a[0]), "r"(a[1]), "r"(a[2]), "r"(a[3]), "r"(b0), "r"(b1));
}
__device__ __forceinline__ void store_pair(float* p, float a, float b) {
    *(float2*)p = make_float2(a, b);
}
__device__ __forceinline__ void store_pair(__nv_bfloat16* p, float a, float b) {
    *(__nv_bfloat162*)p = __floats2bfloat162_rn(a, b);
}
__device__ __forceinline__ float2 bf2(const __nv_bfloat16* p) {
    __nv_bfloat162 v = *(const __nv_bfloat162*)p;
    return make_float2(__bfloat162float(v.x), __bfloat162float(v.y));
}
__device__ __forceinline__ float tanh_fast(float x) {
    float y; asm("tanh.approx.f32 %0, %1;" : "=f"(y) : "f"(x)); return y;
}
// pack two floats to e4m3x2 (lo = first arg)
__device__ __forceinline__ uint16_t f2e4m3x2(float lo, float hi) {
    uint16_t r;
    asm("cvt.rn.satfinite.e4m3x2.f32 %0, %1, %2;" : "=h"(r) : "f"(hi), "f"(lo));
    return r;
}

// ---------------- grid barrier (release/acquire, monotonic) ----------------
__device__ __forceinline__ void grid_barrier(unsigned& gen) {
    __syncthreads();
    if (threadIdx.x == 0) {
        unsigned target = gen + 1;
        unsigned old;
        asm volatile("atom.add.acq_rel.gpu.u32 %0, [%1], 1;"
                     : "=r"(old) : "l"(&g_bar_count) : "memory");
        if (old == target * NBLK - 1) {
            asm volatile("st.release.gpu.u32 [%0], %1;"
                         :: "l"(&g_bar_gen), "r"(target) : "memory");
        } else {
            unsigned cur;
            do {
                asm volatile("ld.acquire.gpu.u32 %0, [%1];"
                             : "=r"(cur) : "l"(&g_bar_gen) : "memory");
            } while (cur < target);
        }
    }
    gen++;
    __syncthreads();
}

// ---------------- fp8 mma GEMM unit: C[256 x 128] = A[256xK] @ W[128xK]^T ----------------
// A, W e4m3 [rows][K] row-major (K bytes per row). C fp32/bf16, values scaled x256.
// 512 threads = 16 warps (4m x 4n), warp tile 64x32.
// K chunk = 64 fp8 = 64B/row: smem layout byte-identical to the proven bf16 unit.
template <typename CT>
__device__ __forceinline__ void mma_unit(
    const uint8_t* __restrict__ A,
    const uint8_t* __restrict__ W,
    CT* __restrict__ C, int ldC,
    int m0, int n0, uint32_t smem0)
{
    const int tid  = threadIdx.x;
    const int lane = tid & 31;
    const int wid  = tid >> 5;          // 0..15
    const int wm   = (wid & 3) * 64;    // warp m-slab
    const int wn   = (wid >> 2) * 32;   // warp n-slab

    const char* baseA = (const char*)(A + (size_t)m0 * Kd);
    const char* baseW = (const char*)(W + (size_t)n0 * Kd);
    uint32_t s_off[3], g_off[3];
    #pragma unroll
    for (int i = 0; i < 2; i++) {        // A: 256 rows x 4 x 16B = 1024 segs
        int seg = tid + i * NTHR;
        int row = seg >> 2, part = seg & 3;
        s_off[i] = row * PITCH + part * 16;
        g_off[i] = row * Kd + part * 16;          // fp8: 1 byte/elem
    }
    {                                    // W: 128 rows x 4 x 16B = 512 segs
        int row = tid >> 2, part = tid & 3;
        s_off[2] = BM * PITCH + row * PITCH + part * 16;
        g_off[2] = row * Kd + part * 16;
    }

    float acc[4][4][4];
    #pragma unroll
    for (int mi = 0; mi < 4; mi++)
        #pragma unroll
        for (int ni = 0; ni < 4; ni++)
            #pragma unroll
            for (int q = 0; q < 4; q++) acc[mi][ni][q] = 0.f;

    // ldmatrix lane address components (same byte pattern as bf16 16x32B tiles)
    const int a_r = (lane & 7) + (lane & 8);
    const int a_k = (lane >> 4) * 16;
    const int b_r = (lane & 7) + ((lane >> 4) << 3);
    const int b_k = (lane & 8) ? 16 : 0;

    auto issue = [&](int c) {
        uint32_t st = smem0 + (uint32_t)(c % NSTAGE) * STAGE_BYTES;
        uint32_t gadd = (uint32_t)c * 64;   // 64 fp8 = 64 bytes per chunk
        cpa16s(st + s_off[0], baseA + g_off[0] + gadd);
        cpa16s(st + s_off[1], baseA + g_off[1] + gadd);
        cpa16s(st + s_off[2], baseW + g_off[2] + gadd);
        cpa_commit();
    };
    issue(0); issue(1); issue(2); issue(3);

    #pragma unroll 1
    for (int c = 0; c < 16; c++) {        // 16 chunks x k64
        if (c < 13) cpa_wait<3>(); else if (c == 13) cpa_wait<2>();
        else if (c == 14) cpa_wait<1>(); else cpa_wait<0>();
        __syncthreads();
        if (c + 4 < 16) issue(c + 4);
        uint32_t st = smem0 + (uint32_t)(c % NSTAGE) * STAGE_BYTES;
        uint32_t sB = st + BM * PITCH;
        #pragma unroll
        for (int ks = 0; ks < 2; ks++) {  // 2 x k32 per chunk
            uint32_t a4[4][4], b4[2][4];
            #pragma unroll
            for (int mi = 0; mi < 4; mi++)
                ldsm_x4(a4[mi], st + (wm + mi * 16 + a_r) * PITCH + a_k + ks * 32);
            #pragma unroll
            for (int bi = 0; bi < 2; bi++)
                ldsm_x4(b4[bi], sB + (wn + bi * 16 + b_r) * PITCH + b_k + ks * 32);
            #pragma unroll
            for (int mi = 0; mi < 4; mi++)
                #pragma unroll
                for (int bi = 0; bi < 2; bi++) {
                    mma16832(acc[mi][2 * bi],     a4[mi], b4[bi][0], b4[bi][1]);
                    mma16832(acc[mi][2 * bi + 1], a4[mi], b4[bi][2], b4[bi][3]);
                }
        }
    }

    const int er = lane >> 2;
    const int ec = (lane & 3) * 2;
    #pragma unroll
    for (int mi = 0; mi < 4; mi++) {
        #pragma unroll
        for (int ni = 0; ni < 4; ni++) {
            CT* p = C + (size_t)(m0 + wm + mi * 16 + er) * ldC + n0 + wn + ni * 8 + ec;
            store_pair(p,            acc[mi][ni][0], acc[mi][ni][1]);
            store_pair(p + 8 * ldC,  acc[mi][ni][2], acc[mi][ni][3]);
        }
    }
    __syncthreads();
}

// ---------------- phase helpers ----------------
__device__ __forceinline__ float sigmoidf_(float x) { return 1.f / (1.f + __expf(-x)); }

__device__ __forceinline__ void gate_phase(
    const __nv_bfloat16* __restrict__ gi, const __nv_bfloat16* __restrict__ gh,
    const float* __restrict__ bi, const float* __restrict__ bh,
    float* __restrict__ h, uint8_t* __restrict__ hb)
{
    const int NP = BH / 2;
    for (int p = blockIdx.x * blockDim.x + threadIdx.x;
         p < NP; p += gridDim.x * blockDim.x) {
        int b = p >> 9;
        int j = (p & 511) * 2;
        const __nv_bfloat16* gib = gi + (size_t)b * G3;
        const __nv_bfloat16* ghb = gh + (size_t)b * G3;
        float2 ir = bf2(gib + j), iz = bf2(gib + 1024 + j), in2 = bf2(gib + 2048 + j);
        float2 hr = bf2(ghb + j), hz = bf2(ghb + 1024 + j), hn = bf2(ghb + 2048 + j);
        float2 br0 = *(const float2*)(bi + j), bz0 = *(const float2*)(bi + 1024 + j),
               bn0 = *(const float2*)(bi + 2048 + j);
        float2 br1 = *(const float2*)(bh + j), bz1 = *(const float2*)(bh + 1024 + j),
               bn1 = *(const float2*)(bh + 2048 + j);
        int idx = b * Hsz + j;
        float2 hp = *(const float2*)(h + idx);

        // preacts are scaled x256 by the fp8 GEMM
        float r0 = sigmoidf_(fmaf(ir.x + hr.x, QINV, br0.x + br1.x));
        float z0 = sigmoidf_(fmaf(iz.x + hz.x, QINV, bz0.x + bz1.x));
        float n0 = tanh_fast(fmaf(in2.x, QINV, bn0.x) + r0 * fmaf(hn.x, QINV, bn1.x));
        float h0 = (1.f - z0) * n0 + z0 * hp.x;

        float r1 = sigmoidf_(fmaf(ir.y + hr.y, QINV, br0.y + br1.y));
        float z1 = sigmoidf_(fmaf(iz.y + hz.y, QINV, bz0.y + bz1.y));
        float n1 = tanh_fast(fmaf(in2.y, QINV, bn0.y) + r1 * fmaf(hn.y, QINV, bn1.y));
        float h1 = (1.f - z1) * n1 + z1 * hp.y;

        *(float2*)(h + idx) = make_float2(h0, h1);
        *(uint16_t*)(hb + idx) = f2e4m3x2(h0 * QSCALE, h1 * QSCALE);
    }
}

// warp-per-row logprob; runs in the GEMM phase on block 147 (no __syncthreads)
__device__ __forceinline__ void logprob_warp(
    int t, int par, const int* __restrict__ target,
    const float* __restrict__ b_out, float* __restrict__ lp)
{
    const int lane = threadIdx.x & 31;
    const int wid  = threadIdx.x >> 5;          // 0..15
    const float* L = g_logits + (size_t)par * Bsz * Vpad;
    for (int b = wid; b < Bsz; b += 16) {
        const float* row = L + (size_t)b * Vpad;
        float m = -1e30f;
        for (int v = lane; v < Vsz; v += 32) m = fmaxf(m, fmaf(row[v], QINV, b_out[v]));
        #pragma unroll
        for (int o = 16; o; o >>= 1) m = fmaxf(m, __shfl_xor_sync(0xffffffffu, m, o));
        float ss = 0.f;
        for (int v = lane; v < Vsz; v += 32) ss += __expf(fmaf(row[v], QINV, b_out[v]) - m);
        #pragma unroll
        for (int o = 16; o; o >>= 1) ss += __shfl_xor_sync(0xffffffffu, ss, o);
        if (lane == 0) {
            int tg = target[b * Tsz + t];
            lp[b] += fmaf(row[tg], QINV, b_out[tg]) - (m + __logf(ss));
        }
    }
}

// ---------------- persistent wavefront kernel ----------------
// Super-step s GEMM phase (all independent):
//   gh1(t=s), gi2+gh2(t=s-1), gi3+gh3(t=s-2), logits(t=s-3) -> parity s&1,
//   gi1(t=s+1), and block 147: logprob(t=s-4) from parity (s-1)&1.
// Gate phase: gate1(s), gate2(s-1), gate3(s-2). 2 barriers/step.
__global__ __launch_bounds__(NTHR, 1) void recur_kernel(
    const int* __restrict__ target,
    const float* __restrict__ b_ih1, const float* __restrict__ b_hh1,
    const float* __restrict__ b_ih2, const float* __restrict__ b_hh2,
    const float* __restrict__ b_ih3, const float* __restrict__ b_hh3,
    const float* __restrict__ b_out,
    float* __restrict__ lp)
{
    extern __shared__ char dsm[];
    const uint32_t smem0 = (smem_u32(dsm) + 127u) & ~127u;
    unsigned gen = 0;
    const int u = blockIdx.x;

    for (int s = -1; s < Tsz + 4; s++) {
        // ---- GEMM phase ----
        if (u < 24) {
            if (s >= 0 && s < Tsz)
                mma_unit(g_h1b, g_wb + 1 * (size_t)WSEG, g_gh1, G3, 0, u * 128, smem0);
        } else if (u < 48) {
            if (s >= 1 && s <= Tsz)
                mma_unit(g_h1b, g_wb + 2 * (size_t)WSEG, g_gi2, G3, 0, (u - 24) * 128, smem0);
        } else if (u < 72) {
            if (s >= 1 && s <= Tsz)
                mma_unit(g_h2b, g_wb + 3 * (size_t)WSEG, g_gh2, G3, 0, (u - 48) * 128, smem0);
        } else if (u < 96) {
            if (s >= 2 && s <= Tsz + 1)
                mma_unit(g_h2b, g_wb + 4 * (size_t)WSEG, g_gi3, G3, 0, (u - 72) * 128, smem0);
        } else if (u < 120) {
            if (s >= 2 && s <= Tsz + 1)
                mma_unit(g_h3b, g_wb + 5 * (size_t)WSEG, g_gh3, G3, 0, (u - 96) * 128, smem0);
        } else if (u < 123) {
            if (s >= 3 && s <= Tsz + 2)
                mma_unit(g_h3b, g_wout,
                         g_logits + (size_t)(s & 1) * Bsz * Vpad, Vpad,
                         0, (u - 120) * 128, smem0);
        } else if (u < 147) {
            int tg1 = s + 1;                   // gi1 for the NEXT super-step
            if (tg1 >= 0 && tg1 < Tsz)
                mma_unit(g_xb + (size_t)tg1 * Bsz * Kd, g_wb /* w_ih1 */,
                         g_gi1 + (size_t)tg1 * Bsz * G3, G3, 0, (u - 123) * 128, smem0);
        } else {
            if (s >= 4 && s <= Tsz + 3)
                logprob_warp(s - 4, (s - 1) & 1, target, b_out, lp);
        }
        grid_barrier(gen);

        // ---- gate phase ----
        if (s >= 0 && s < Tsz)
            gate_phase(g_gi1 + (size_t)s * Bsz * G3, g_gh1, b_ih1, b_hh1, g_h1, g_h1b);
        if (s >= 1 && s <= Tsz)
            gate_phase(g_gi2, g_gh2, b_ih2, b_hh2, g_h2, g_h2b);
        if (s >= 2 && s <= Tsz + 1)
            gate_phase(g_gi3, g_gh3, b_ih3, b_hh3, g_h3, g_h3b);
        grid_barrier(gen);
    }
}

// ---------------- setup kernels ----------------
__global__ __launch_bounds__(256) void init_misc(const float* __restrict__ w_out,
                                                 float* __restrict__ lp)
{
    // pairs over Vpad*Kd (even)
    for (int i = blockIdx.x * blockDim.x + threadIdx.x;
         i < Vpad * Kd / 2; i += gridDim.x * blockDim.x) {
        int e0 = 2 * i;
        int row = e0 >> 10;
        float a = (row < Vsz) ? w_out[e0] * QSCALE : 0.f;
        float b = (row < Vsz) ? w_out[e0 + 1] * QSCALE : 0.f;
        *(uint16_t*)(g_wout + e0) = f2e4m3x2(a, b);
        if (e0 < BH) {
            g_h1[e0] = 0.f; g_h1[e0 + 1] = 0.f;
            g_h2[e0] = 0.f; g_h2[e0 + 1] = 0.f;
            g_h3[e0] = 0.f; g_h3[e0 + 1] = 0.f;
            *(uint16_t*)(g_h1b + e0) = 0;
            *(uint16_t*)(g_h2b + e0) = 0;
            *(uint16_t*)(g_h3b + e0) = 0;
        }
        if (e0 < Bsz) { lp[e0] = 0.f; lp[e0 + 1] = 0.f; }
        if (e0 == 0) { g_bar_count = 0u; g_bar_gen = 0u; }
    }
}

__global__ __launch_bounds__(256) void conv_weights(
    const float* __restrict__ w0, const float* __restrict__ w1,
    const float* __restrict__ w2, const float* __restrict__ w3,
    const float* __restrict__ w4, const float* __restrict__ w5)
{
    const size_t NPAIR = 6 * (size_t)WSEG / 2;
    for (size_t i = (size_t)blockIdx.x * blockDim.x + threadIdx.x;
         i < NPAIR; i += (size_t)gridDim.x * blockDim.x) {
        size_t e0 = 2 * i;
        int seg = (int)(e0 / WSEG);
        size_t off = e0 % WSEG;
        const float* s = seg == 0 ? w0 : seg == 1 ? w1 : seg == 2 ? w2
                       : seg == 3 ? w3 : seg == 4 ? w4 : w5;
        *(uint16_t*)(g_wb + e0) = f2e4m3x2(s[off] * QSCALE, s[off + 1] * QSCALE);
    }
}

__global__ __launch_bounds__(256) void gather_x(
    const int* __restrict__ target, const int* __restrict__ bosp,
    const float* __restrict__ emb)
{
    const int nq = Tsz * Bsz * (Kd / 4);
    for (int i = blockIdx.x * blockDim.x + threadIdx.x; i < nq; i += gridDim.x * blockDim.x) {
        int m  = i / (Kd / 4);
        int kq = i % (Kd / 4);
        int t = m >> 8, b = m & 255;
        int tok = (t == 0) ? bosp[0] : target[(b << 7) + t - 1];
        float4 v = *(const float4*)(emb + (size_t)tok * Kd + kq * 4);
        uint32_t pk = (uint32_t)f2e4m3x2(v.x * QSCALE, v.y * QSCALE)
                    | ((uint32_t)f2e4m3x2(v.z * QSCALE, v.w * QSCALE) << 16);
        *(uint32_t*)(g_xb + (size_t)m * Kd + kq * 4) = pk;
    }
}

// ---------------- launch ----------------
extern "C" void kernel_launch(void* const* d_in, const int* in_sizes, int n_in,
                              void* d_out, int out_size)
{
    (void)in_sizes; (void)n_in; (void)out_size;
    const int*   target = (const int*)  d_in[0];
    const int*   bos    = (const int*)  d_in[1];
    const float* emb    = (const float*)d_in[2];
    const float* w_ih1  = (const float*)d_in[3];
    const float* w_hh1  = (const float*)d_in[4];
    const float* b_ih1  = (const float*)d_in[5];
    const float* b_hh1  = (const float*)d_in[6];
    const float* w_ih2  = (const float*)d_in[7];
    const float* w_hh2  = (const float*)d_in[8];
    const float* b_ih2  = (const float*)d_in[9];
    const float* b_hh2  = (const float*)d_in[10];
    const float* w_ih3  = (const float*)d_in[11];
    const float* w_hh3  = (const float*)d_in[12];
    const float* b_ih3  = (const float*)d_in[13];
    const float* b_hh3  = (const float*)d_in[14];
    const float* w_out  = (const float*)d_in[15];
    const float* b_out  = (const float*)d_in[16];
    float* lp = (float*)d_out;

    cudaFuncSetAttribute(recur_kernel,
        cudaFuncAttributeMaxDynamicSharedMemorySize, SMEM_DYN);

    init_misc<<<(Vpad * Kd / 2 + 255) / 256, 256>>>(w_out, lp);
    conv_weights<<<8192, 256>>>(w_ih1, w_hh1, w_ih2, w_hh2, w_ih3, w_hh3);
    gather_x<<<8192, 256>>>(target, bos, emb);

    recur_kernel<<<NBLK, NTHR, SMEM_DYN>>>(target,
                                b_ih1, b_hh1, b_ih2, b_hh2, b_ih3, b_hh3,
                                b_out, lp);
}

// round 16
// speedup vs baseline: 1.1854x; 1.0499x over previous
#include <cuda_runtime.h>
#include <cuda_bf16.h>
#include <math.h>
#include <stdint.h>

#define Bsz  256
#define Tsz  128
#define Hsz  1024
#define G3   3072
#define Vsz  348
#define Vpad 384
#define Kd   1024
#define NBLK 148
#define NTHR 512
#define WSEG 3145728   // 3072*1024
#define BH   (Bsz * Hsz)

#define QSCALE 16.f            // fp8 quantization scale (both operands)
#define QINV   (1.f / 256.f)   // preactivation descale

// GEMM config: BM=256 (=full M), BN=128, fp8 K-chunk = 64 elems (64B/row),
// 512 threads, warp tile 64x32, 6-stage cp.async ring, 1 sync per chunk.
#define BM 256
#define BN 128
#define PITCH 80                         // smem row pitch bytes (64B data + pad)
#define STAGE_BYTES ((BM + BN) * PITCH)  // 30720
#define NSTAGE 6
#define SM_BIAS (NSTAGE * STAGE_BYTES)   // 184320: bias table after the ring
#define BIAS_ELEMS (3 * 4096)            // [l][rsum|zsum|bn_i|bn_h] x 1024, bf16
#define SMEM_DYN (SM_BIAS + BIAS_ELEMS * 2 + 256)   // 209152

// ---------------- scratch (device globals; no allocs allowed) ----------------
__device__ __nv_bfloat16  g_gi1[(size_t)Tsz * Bsz * G3];   // scaled x256
__device__ uint8_t        g_xb[(size_t)Tsz * Bsz * Kd];    // e4m3, x16
__device__ uint8_t        g_wb[6 * (size_t)WSEG];          // e4m3, x16
__device__ uint8_t        g_wout[Vpad * Kd];               // e4m3, x16
__device__ __nv_bfloat16  g_biasv[BIAS_ELEMS];             // bf16 bias table
__device__ __nv_bfloat16  g_gh1[Bsz * G3];                 // scaled x256
__device__ __nv_bfloat16  g_gi2[Bsz * G3], g_gh2[Bsz * G3];
__device__ __nv_bfloat16  g_gi3[Bsz * G3], g_gh3[Bsz * G3];
__device__ float          g_h1[BH], g_h2[BH], g_h3[BH];
__device__ uint8_t        g_h1b[BH], g_h2b[BH], g_h3b[BH]; // e4m3, x16
__device__ float          g_logits[2 * Bsz * Vpad];        // scaled x256, parity buffers
__device__ unsigned       g_bar_count;   // monotonic
__device__ unsigned       g_bar_gen;     // monotonic

namespace {
struct Boot {
    Boot() { void* p = nullptr; cudaGetSymbolAddress(&p, g_gi1); }
};
static Boot boot_;
}

// ---------------- low-level helpers ----------------
__device__ __forceinline__ uint32_t smem_u32(const void* p) {
    return (uint32_t)__cvta_generic_to_shared(p);
}
__device__ __forceinline__ void cpa16s(uint32_t saddr, const void* g) {
    asm volatile("cp.async.cg.shared.global [%0], [%1], 16;" :: "r"(saddr), "l"(g));
}
__device__ __forceinline__ void cpa_commit() {
    asm volatile("cp.async.commit_group;");
}
template <int N>
__device__ __forceinline__ void cpa_wait() {
    asm volatile("cp.async.wait_group %0;" :: "n"(N));
}
__device__ __forceinline__ void ldsm_x4(uint32_t* r, uint32_t a) {
    asm volatile("ldmatrix.sync.aligned.m8n8.x4.shared.b16 {%0,%1,%2,%3}, [%4];"
        : "=r"(r[0]), "=r"(r[1]), "=r"(r[2]), "=r"(r[3]) : "r"(a));
}
// fp8 e4m3 MMA: D[16x8] += A[16x32] * B[8x32]^T, fp32 accum
__device__ __forceinline__ void mma16832(float* c, const uint32_t* a, uint32_t b0, uint32_t b1) {
    asm volatile(
        "mma.sync.aligned.m16n8k32.row.col.f32.e4m3.e4m3.f32 "
        "{%0,%1,%2,%3},{%4,%5,%6,%7},{%8,%9},{%0,%1,%2,%3};"
        : "+f"(c[0]), "+f"(c[1]), "+f"(c[2]), "+f"(c[3])
        : "r"(a[0]), "r"(a[1]), "r"(a[2]), "r"(a[3]), "r"(b0), "r"(b1));
}
__device__ __forceinline__ void store_pair(float* p, float a, float b) {
    *(float2*)p = make_float2(a, b);
}
__device__ __forceinline__ void store_pair(__nv_bfloat16* p, float a, float b) {
    *(__nv_bfloat162*)p = __floats2bfloat162_rn(a, b);
}
__device__ __forceinline__ float2 bf2(const __nv_bfloat16* p) {
    __nv_bfloat162 v = *(const __nv_bfloat162*)p;
    return make_float2(__bfloat162float(v.x), __bfloat162float(v.y));
}
__device__ __forceinline__ float tanh_fast(float x) {
    float y; asm("tanh.approx.f32 %0, %1;" : "=f"(y) : "f"(x)); return y;
}
// pack two floats to e4m3x2 (lo = first arg)
__device__ __forceinline__ uint16_t f2e4m3x2(float lo, float hi) {
    uint16_t r;
    asm("cvt.rn.satfinite.e4m3x2.f32 %0, %1, %2;" : "=h"(r) : "f"(hi), "f"(lo));
    return r;
}

// ---------------- grid barrier (release/acquire, monotonic) ----------------
__device__ __forceinline__ void grid_barrier(unsigned& gen) {
    __syncthreads();
    if (threadIdx.x == 0) {
        unsigned target = gen + 1;
        unsigned old;
        asm volatile("atom.add.acq_rel.gpu.u32 %0, [%1], 1;"
                     : "=r"(old) : "l"(&g_bar_count) : "memory");
        if (old == target * NBLK - 1) {
            asm volatile("st.release.gpu.u32 [%0], %1;"
                         :: "l"(&g_bar_gen), "r"(target) : "memory");
        } else {
            unsigned cur;
            do {
                asm volatile("ld.acquire.gpu.u32 %0, [%1];"
                             : "=r"(cur) : "l"(&g_bar_gen) : "memory");
            } while (cur < target);
        }
    }
    gen++;
    __syncthreads();
}

// ---------------- fp8 mma GEMM unit: C[256 x 128] = A[256xK] @ W[128xK]^T ----------------
// A, W e4m3 [rows][K] row-major (K bytes per row). C fp32/bf16, values scaled x256.
// 512 threads = 16 warps (4m x 4n), warp tile 64x32.
template <typename CT>
__device__ __forceinline__ void mma_unit(
    const uint8_t* __restrict__ A,
    const uint8_t* __restrict__ W,
    CT* __restrict__ C, int ldC,
    int m0, int n0, uint32_t smem0)
{
    const int tid  = threadIdx.x;
    const int lane = tid & 31;
    const int wid  = tid >> 5;          // 0..15
    const int wm   = (wid & 3) * 64;    // warp m-slab
    const int wn   = (wid >> 2) * 32;   // warp n-slab

    const char* baseA = (const char*)(A + (size_t)m0 * Kd);
    const char* baseW = (const char*)(W + (size_t)n0 * Kd);
    uint32_t s_off[3], g_off[3];
    #pragma unroll
    for (int i = 0; i < 2; i++) {        // A: 256 rows x 4 x 16B = 1024 segs
        int seg = tid + i * NTHR;
        int row = seg >> 2, part = seg & 3;
        s_off[i] = row * PITCH + part * 16;
        g_off[i] = row * Kd + part * 16;          // fp8: 1 byte/elem
    }
    {                                    // W: 128 rows x 4 x 16B = 512 segs
        int row = tid >> 2, part = tid & 3;
        s_off[2] = BM * PITCH + row * PITCH + part * 16;
        g_off[2] = row * Kd + part * 16;
    }

    float acc[4][4][4];
    #pragma unroll
    for (int mi = 0; mi < 4; mi++)
        #pragma unroll
        for (int ni = 0; ni < 4; ni++)
            #pragma unroll
            for (int q = 0; q < 4; q++) acc[mi][ni][q] = 0.f;

    const int a_r = (lane & 7) + (lane & 8);
    const int a_k = (lane >> 4) * 16;
    const int b_r = (lane & 7) + ((lane >> 4) << 3);
    const int b_k = (lane & 8) ? 16 : 0;

    auto issue = [&](int c) {
        uint32_t st = smem0 + (uint32_t)(c % NSTAGE) * STAGE_BYTES;
        uint32_t gadd = (uint32_t)c * 64;   // 64 fp8 = 64 bytes per chunk
        cpa16s(st + s_off[0], baseA + g_off[0] + gadd);
        cpa16s(st + s_off[1], baseA + g_off[1] + gadd);
        cpa16s(st + s_off[2], baseW + g_off[2] + gadd);
        cpa_commit();
    };
    issue(0); issue(1); issue(2); issue(3);

    #pragma unroll 1
    for (int c = 0; c < 16; c++) {        // 16 chunks x k64
        // issue BEFORE wait: stage (c+4)%6 == (c-2)%6 was fully consumed
        // before the previous __syncthreads (all warps are past it).
        if (c + 4 < 16) issue(c + 4);
        if (c < 12) cpa_wait<4>(); else if (c == 12) cpa_wait<3>();
        else if (c == 13) cpa_wait<2>(); else if (c == 14) cpa_wait<1>();
        else cpa_wait<0>();
        __syncthreads();
        uint32_t st = smem0 + (uint32_t)(c % NSTAGE) * STAGE_BYTES;
        uint32_t sB = st + BM * PITCH;
        #pragma unroll
        for (int ks = 0; ks < 2; ks++) {  // 2 x k32 per chunk
            uint32_t a4[4][4], b4[2][4];
            #pragma unroll
            for (int mi = 0; mi < 4; mi++)
                ldsm_x4(a4[mi], st + (wm + mi * 16 + a_r) * PITCH + a_k + ks * 32);
            #pragma unroll
            for (int bi = 0; bi < 2; bi++)
                ldsm_x4(b4[bi], sB + (wn + bi * 16 + b_r) * PITCH + b_k + ks * 32);
            #pragma unroll
            for (int mi = 0; mi < 4; mi++)
                #pragma unroll
                for (int bi = 0; bi < 2; bi++) {
                    mma16832(acc[mi][2 * bi],     a4[mi], b4[bi][0], b4[bi][1]);
                    mma16832(acc[mi][2 * bi + 1], a4[mi], b4[bi][2], b4[bi][3]);
                }
        }
    }

    const int er = lane >> 2;
    const int ec = (lane & 3) * 2;
    #pragma unroll
    for (int mi = 0; mi < 4; mi++) {
        #pragma unroll
        for (int ni = 0; ni < 4; ni++) {
            CT* p = C + (size_t)(m0 + wm + mi * 16 + er) * ldC + n0 + wn + ni * 8 + ec;
            store_pair(p,            acc[mi][ni][0], acc[mi][ni][1]);
            store_pair(p + 8 * ldC,  acc[mi][ni][2], acc[mi][ni][3]);
        }
    }
    __syncthreads();
}

// ---------------- phase helpers ----------------
__device__ __forceinline__ float sigmoidf_(float x) { return 1.f / (1.f + __expf(-x)); }

// gate for one layer, TWO batch rows (b0, b0+1), column pair j.
// Loads batched up-front for MLP; biases from shared memory.
__device__ __forceinline__ void gate_layer(
    const __nv_bfloat16* __restrict__ gi, const __nv_bfloat16* __restrict__ gh,
    const __nv_bfloat16* __restrict__ bb,   // smem bias base for this layer
    float* __restrict__ h, uint8_t* __restrict__ hb,
    int b0, int j)
{
    const __nv_bfloat16* gi0 = gi + (size_t)b0 * G3 + j;
    const __nv_bfloat16* gh0 = gh + (size_t)b0 * G3 + j;
    const int idx0 = b0 * Hsz + j;

    // ---- batched loads (independent; compiler hoists) ----
    float2 ir0 = bf2(gi0),        iz0 = bf2(gi0 + 1024), in0 = bf2(gi0 + 2048);
    float2 ir1 = bf2(gi0 + G3),   iz1 = bf2(gi0 + G3 + 1024), in1 = bf2(gi0 + G3 + 2048);
    float2 hr0 = bf2(gh0),        hz0 = bf2(gh0 + 1024), hn0 = bf2(gh0 + 2048);
    float2 hr1 = bf2(gh0 + G3),   hz1 = bf2(gh0 + G3 + 1024), hn1 = bf2(gh0 + G3 + 2048);
    float2 hp0 = *(const float2*)(h + idx0);
    float2 hp1 = *(const float2*)(h + idx0 + Hsz);
    float2 br  = bf2(bb + j),        bz  = bf2(bb + 1024 + j);
    float2 bni = bf2(bb + 2048 + j), bnh = bf2(bb + 3072 + j);

    // ---- row 0 ----
    float r0x = sigmoidf_(fmaf(ir0.x + hr0.x, QINV, br.x));
    float r0y = sigmoidf_(fmaf(ir0.y + hr0.y, QINV, br.y));
    float z0x = sigmoidf_(fmaf(iz0.x + hz0.x, QINV, bz.x));
    float z0y = sigmoidf_(fmaf(iz0.y + hz0.y, QINV, bz.y));
    float n0x = tanh_fast(fmaf(in0.x, QINV, bni.x) + r0x * fmaf(hn0.x, QINV, bnh.x));
    float n0y = tanh_fast(fmaf(in0.y, QINV, bni.y) + r0y * fmaf(hn0.y, QINV, bnh.y));
    float h0x = (1.f - z0x) * n0x + z0x * hp0.x;
    float h0y = (1.f - z0y) * n0y + z0y * hp0.y;

    // ---- row 1 ----
    float r1x = sigmoidf_(fmaf(ir1.x + hr1.x, QINV, br.x));
    float r1y = sigmoidf_(fmaf(ir1.y + hr1.y, QINV, br.y));
    float z1x = sigmoidf_(fmaf(iz1.x + hz1.x, QINV, bz.x));
    float z1y = sigmoidf_(fmaf(iz1.y + hz1.y, QINV, bz.y));
    float n1x = tanh_fast(fmaf(in1.x, QINV, bni.x) + r1x * fmaf(hn1.x, QINV, bnh.x));
    float n1y = tanh_fast(fmaf(in1.y, QINV, bni.y) + r1y * fmaf(hn1.y, QINV, bnh.y));
    float h1x = (1.f - z1x) * n1x + z1x * hp1.x;
    float h1y = (1.f - z1y) * n1y + z1y * hp1.y;

    *(float2*)(h + idx0)        = make_float2(h0x, h0y);
    *(float2*)(h + idx0 + Hsz)  = make_float2(h1x, h1y);
    *(uint16_t*)(hb + idx0)       = f2e4m3x2(h0x * QSCALE, h0y * QSCALE);
    *(uint16_t*)(hb + idx0 + Hsz) = f2e4m3x2(h1x * QSCALE, h1y * QSCALE);
}

// warp-per-row logprob; runs in the GEMM phase on block 147 (no __syncthreads)
__device__ __forceinline__ void logprob_warp(
    int t, int par, const int* __restrict__ target,
    const float* __restrict__ b_out, float* __restrict__ lp)
{
    const int lane = threadIdx.x & 31;
    const int wid  = threadIdx.x >> 5;          // 0..15
    const float* L = g_logits + (size_t)par * Bsz * Vpad;
    for (int b = wid; b < Bsz; b += 16) {
        const float* row = L + (size_t)b * Vpad;
        float m = -1e30f;
        for (int v = lane; v < Vsz; v += 32) m = fmaxf(m, fmaf(row[v], QINV, b_out[v]));
        #pragma unroll
        for (int o = 16; o; o >>= 1) m = fmaxf(m, __shfl_xor_sync(0xffffffffu, m, o));
        float ss = 0.f;
        for (int v = lane; v < Vsz; v += 32) ss += __expf(fmaf(row[v], QINV, b_out[v]) - m);
        #pragma unroll
        for (int o = 16; o; o >>= 1) ss += __shfl_xor_sync(0xffffffffu, ss, o);
        if (lane == 0) {
            int tg = target[b * Tsz + t];
            lp[b] += fmaf(row[tg], QINV, b_out[tg]) - (m + __logf(ss));
        }
    }
}

// ---------------- persistent wavefront kernel ----------------
// Super-step s GEMM phase (all independent):
//   gh1(t=s), gi2+gh2(t=s-1), gi3+gh3(t=s-2), logits(t=s-3) -> parity s&1,
//   gi1(t=s+1), and block 147: logprob(t=s-4) from parity (s-1)&1.
// Gate phase: blocks 0..127, block u owns rows (2u, 2u+1), thread t cols (2t, 2t+1).
__global__ __launch_bounds__(NTHR, 1) void recur_kernel(
    const int* __restrict__ target,
    const float* __restrict__ b_out,
    float* __restrict__ lp)
{
    extern __shared__ char dsm[];
    const uint32_t smem0 = (smem_u32(dsm) + 127u) & ~127u;
    const uint32_t pad = smem0 - smem_u32(dsm);
    const __nv_bfloat16* sbias = (const __nv_bfloat16*)(dsm + pad + SM_BIAS);
    unsigned gen = 0;
    const int u = blockIdx.x;
    const int tid = threadIdx.x;

    // stage bias table into smem once
    {
        uint32_t* dst = (uint32_t*)(dsm + pad + SM_BIAS);
        const uint32_t* src = (const uint32_t*)g_biasv;
        for (int i = tid; i < BIAS_ELEMS / 2; i += NTHR) dst[i] = src[i];
    }
    __syncthreads();

    for (int s = -1; s < Tsz + 4; s++) {
        // ---- GEMM phase ----
        if (u < 24) {
            if (s >= 0 && s < Tsz)
                mma_unit(g_h1b, g_wb + 1 * (size_t)WSEG, g_gh1, G3, 0, u * 128, smem0);
        } else if (u < 48) {
            if (s >= 1 && s <= Tsz)
                mma_unit(g_h1b, g_wb + 2 * (size_t)WSEG, g_gi2, G3, 0, (u - 24) * 128, smem0);
        } else if (u < 72) {
            if (s >= 1 && s <= Tsz)
                mma_unit(g_h2b, g_wb + 3 * (size_t)WSEG, g_gh2, G3, 0, (u - 48) * 128, smem0);
        } else if (u < 96) {
            if (s >= 2 && s <= Tsz + 1)
                mma_unit(g_h2b, g_wb + 4 * (size_t)WSEG, g_gi3, G3, 0, (u - 72) * 128, smem0);
        } else if (u < 120) {
            if (s >= 2 && s <= Tsz + 1)
                mma_unit(g_h3b, g_wb + 5 * (size_t)WSEG, g_gh3, G3, 0, (u - 96) * 128, smem0);
        } else if (u < 123) {
            if (s >= 3 && s <= Tsz + 2)
                mma_unit(g_h3b, g_wout,
                         g_logits + (size_t)(s & 1) * Bsz * Vpad, Vpad,
                         0, (u - 120) * 128, smem0);
        } else if (u < 147) {
            int tg1 = s + 1;                   // gi1 for the NEXT super-step
            if (tg1 >= 0 && tg1 < Tsz)
                mma_unit(g_xb + (size_t)tg1 * Bsz * Kd, g_wb /* w_ih1 */,
                         g_gi1 + (size_t)tg1 * Bsz * G3, G3, 0, (u - 123) * 128, smem0);
        } else {
            if (s >= 4 && s <= Tsz + 3)
                logprob_warp(s - 4, (s - 1) & 1, target, b_out, lp);
        }
        grid_barrier(gen);

        // ---- gate phase (blocks 0..127) ----
        if (u < 128) {
            const int b0 = 2 * u;
            const int j  = 2 * tid;
            if (s >= 0 && s < Tsz)
                gate_layer(g_gi1 + (size_t)s * Bsz * G3, g_gh1, sbias,
                           g_h1, g_h1b, b0, j);
            if (s >= 1 && s <= Tsz)
                gate_layer(g_gi2, g_gh2, sbias + 4096, g_h2, g_h2b, b0, j);
            if (s >= 2 && s <= Tsz + 1)
                gate_layer(g_gi3, g_gh3, sbias + 8192, g_h3, g_h3b, b0, j);
        }
        grid_barrier(gen);
    }
}

// ---------------- setup kernels ----------------
__global__ __launch_bounds__(256) void init_misc(
    const float* __restrict__ w_out, float* __restrict__ lp,
    const float* __restrict__ bi1, const float* __restrict__ bh1,
    const float* __restrict__ bi2, const float* __restrict__ bh2,
    const float* __restrict__ bi3, const float* __restrict__ bh3)
{
    for (int i = blockIdx.x * blockDim.x + threadIdx.x;
         i < Vpad * Kd / 2; i += gridDim.x * blockDim.x) {
        int e0 = 2 * i;
        int row = e0 >> 10;
        float a = (row < Vsz) ? w_out[e0] * QSCALE : 0.f;
        float b = (row < Vsz) ? w_out[e0 + 1] * QSCALE : 0.f;
        *(uint16_t*)(g_wout + e0) = f2e4m3x2(a, b);
        if (e0 < BH) {
            g_h1[e0] = 0.f; g_h1[e0 + 1] = 0.f;
            g_h2[e0] = 0.f; g_h2[e0 + 1] = 0.f;
            g_h3[e0] = 0.f; g_h3[e0 + 1] = 0.f;
            *(uint16_t*)(g_h1b + e0) = 0;
            *(uint16_t*)(g_h2b + e0) = 0;
            *(uint16_t*)(g_h3b + e0) = 0;
        }
        if (e0 < Bsz) { lp[e0] = 0.f; lp[e0 + 1] = 0.f; }
        if (e0 == 0) { g_bar_count = 0u; g_bar_gen = 0u; }
        // bias table: per layer [rsum | zsum | bn_i | bn_h], 1024 each
        if (i < BIAS_ELEMS / 2) {
            int l = e0 >> 12;
            int r = e0 & 4095;
            const float* bi = l == 0 ? bi1 : l == 1 ? bi2 : bi3;
            const float* bh = l == 0 ? bh1 : l == 1 ? bh2 : bh3;
            int sec = r >> 10, k = r & 1023;
            float v0, v1;
            if (sec == 0)      { v0 = bi[k] + bh[k];             v1 = bi[k + 1] + bh[k + 1]; }
            else if (sec == 1) { v0 = bi[1024 + k] + bh[1024 + k]; v1 = bi[1025 + k] + bh[1025 + k]; }
            else if (sec == 2) { v0 = bi[2048 + k];              v1 = bi[2049 + k]; }
            else               { v0 = bh[2048 + k];              v1 = bh[2049 + k]; }
            *(__nv_bfloat162*)(g_biasv + e0) = __floats2bfloat162_rn(v0, v1);
        }
    }
}

__global__ __launch_bounds__(256) void conv_weights(
    const float* __restrict__ w0, const float* __restrict__ w1,
    const float* __restrict__ w2, const float* __restrict__ w3,
    const float* __restrict__ w4, const float* __restrict__ w5)
{
    const size_t NPAIR = 6 * (size_t)WSEG / 2;
    for (size_t i = (size_t)blockIdx.x * blockDim.x + threadIdx.x;
         i < NPAIR; i += (size_t)gridDim.x * blockDim.x) {
        size_t e0 = 2 * i;
        int seg = (int)(e0 / WSEG);
        size_t off = e0 % WSEG;
        const float* s = seg == 0 ? w0 : seg == 1 ? w1 : seg == 2 ? w2
                       : seg == 3 ? w3 : seg == 4 ? w4 : w5;
        *(uint16_t*)(g_wb + e0) = f2e4m3x2(s[off] * QSCALE, s[off + 1] * QSCALE);
    }
}

__global__ __launch_bounds__(256) void gather_x(
    const int* __restrict__ target, const int* __restrict__ bosp,
    const float* __restrict__ emb)
{
    const int nq = Tsz * Bsz * (Kd / 4);
    for (int i = blockIdx.x * blockDim.x + threadIdx.x; i < nq; i += gridDim.x * blockDim.x) {
        int m  = i / (Kd / 4);
        int kq = i % (Kd / 4);
        int t = m >> 8, b = m & 255;
        int tok = (t == 0) ? bosp[0] : target[(b << 7) + t - 1];
        float4 v = *(const float4*)(emb + (size_t)tok * Kd + kq * 4);
        uint32_t pk = (uint32_t)f2e4m3x2(v.x * QSCALE, v.y * QSCALE)
                    | ((uint32_t)f2e4m3x2(v.z * QSCALE, v.w * QSCALE) << 16);
        *(uint32_t*)(g_xb + (size_t)m * Kd + kq * 4) = pk;
    }
}

// ---------------- launch ----------------
extern "C" void kernel_launch(void* const* d_in, const int* in_sizes, int n_in,
                              void* d_out, int out_size)
{
    (void)in_sizes; (void)n_in; (void)out_size;
    const int*   target = (const int*)  d_in[0];
    const int*   bos    = (const int*)  d_in[1];
    const float* emb    = (const float*)d_in[2];
    const float* w_ih1  = (const float*)d_in[3];
    const float* w_hh1  = (const float*)d_in[4];
    const float* b_ih1  = (const float*)d_in[5];
    const float* b_hh1  = (const float*)d_in[6];
    const float* w_ih2  = (const float*)d_in[7];
    const float* w_hh2  = (const float*)d_in[8];
    const float* b_ih2  = (const float*)d_in[9];
    const float* b_hh2  = (const float*)d_in[10];
    const float* w_ih3  = (const float*)d_in[11];
    const float* w_hh3  = (const float*)d_in[12];
    const float* b_ih3  = (const float*)d_in[13];
    const float* b_hh3  = (const float*)d_in[14];
    const float* w_out  = (const float*)d_in[15];
    const float* b_out  = (const float*)d_in[16];
    float* lp = (float*)d_out;

    cudaFuncSetAttribute(recur_kernel,
        cudaFuncAttributeMaxDynamicSharedMemorySize, SMEM_DYN);

    init_misc<<<(Vpad * Kd / 2 + 255) / 256, 256>>>(w_out, lp,
        b_ih1, b_hh1, b_ih2, b_hh2, b_ih3, b_hh3);
    conv_weights<<<8192, 256>>>(w_ih1, w_hh1, w_ih2, w_hh2, w_ih3, w_hh3);
    gather_x<<<8192, 256>>>(target, bos, emb);

    recur_kernel<<<NBLK, NTHR, SMEM_DYN>>>(target, b_out, lp);
}